// round 3
// baseline (speedup 1.0000x reference)
#include <cuda_runtime.h>

#define RES 512
#define NBLOBS 2048
#define TILE 32          // tile is 32x32 pixels
#define NTHREADS 256     // 32 x 8
#define PPT 4            // pixels per thread (along y, stride 8 rows)
#define QCUT 6.0f        // cutoff radius in "sigma" units; exp(-18) ~ 1.5e-8

// Scratch (no allocations allowed): per-blob cull box + derived params.
__device__ float4 g_cull[NBLOBS];          // (bx, by, ex, ey)
__device__ float4 g_parm[NBLOBS * 3];      // (bx,by,A,B) (C,D,aS,bS) (r,g,b,-)

// ---------------------------------------------------------------------------
// Prep: per-blob derived parameters (runs once per launch, 2048 threads).
//   a = (c*dx + s*dy) * k/sx ,  b = (-s*dx + c*dy) * k/sy , k = sqrt(0.5*log2e)
//   g = exp(-0.5*((xr/sx)^2+(yr/sy)^2)) = 2^(-(a^2+b^2))
// ---------------------------------------------------------------------------
__global__ void splat_prep_kernel(const float* __restrict__ blobs) {
    int i = blockIdx.x * blockDim.x + threadIdx.x;
    if (i >= NBLOBS) return;
    const float* bl = blobs + i * 8;
    float bx = bl[0], by = bl[1];
    float sx = bl[2], sy = bl[3];
    float rot = bl[4];
    float cr = bl[5], cg = bl[6], cb = bl[7];

    float s, c;
    sincosf(rot, &s, &c);

    const float kk = 0.84932180f;      // sqrt(0.5 * log2(e))
    float isx = kk / sx;
    float isy = kk / sy;
    float A = c * isx, B = s * isx;    // a = A*dx + B*dy
    float C = -s * isy, D = c * isy;   // b = C*dx + D*dy

    const float dlt = 8.0f / (float)RES;   // y stride between a thread's pixels
    float aS = B * dlt;
    float bS = D * dlt;

    // AABB half-extents of the QCUT-sigma ellipse
    float ex = QCUT * sqrtf(c * c * sx * sx + s * s * sy * sy);
    float ey = QCUT * sqrtf(s * s * sx * sx + c * c * sy * sy);

    g_cull[i] = make_float4(bx, by, ex, ey);
    g_parm[i * 3 + 0] = make_float4(bx, by, A, B);
    g_parm[i * 3 + 1] = make_float4(C, D, aS, bS);
    g_parm[i * 3 + 2] = make_float4(cr, cg, cb, 0.0f);
}

// ---------------------------------------------------------------------------
// Render: one CTA per 32x32 tile; 256 threads; 4 pixels per thread (y-strided).
// Per 256-blob batch: deterministic ballot/prefix compaction of survivors into
// shared, then all threads evaluate the survivor list.
// ---------------------------------------------------------------------------
__global__ void __launch_bounds__(NTHREADS) splat_render_kernel(float* __restrict__ out) {
    __shared__ float4 sP[NTHREADS][3];
    __shared__ int sWarp[8];

    const int tx = threadIdx.x;            // 0..31
    const int ty = threadIdx.y;            // 0..7
    const int tid = ty * 32 + tx;
    const int lane = tid & 31;
    const int wid = tid >> 5;

    const int x = blockIdx.x * TILE + tx;
    const int y0 = blockIdx.y * TILE + ty;
    const float inv = 1.0f / (float)RES;
    const float px = ((float)x + 0.5f) * inv;
    const float py = ((float)y0 + 0.5f) * inv;

    const float tw = (float)TILE * inv;
    const float tX0 = (float)blockIdx.x * tw;
    const float tX1 = tX0 + tw;
    const float tY0 = (float)blockIdx.y * tw;
    const float tY1 = tY0 + tw;

    float aR[PPT], aG[PPT], aB[PPT];
#pragma unroll
    for (int k = 0; k < PPT; ++k) { aR[k] = 0.0f; aG[k] = 0.0f; aB[k] = 0.0f; }

    for (int base = 0; base < NBLOBS; base += NTHREADS) {
        const int i = base + tid;
        const float4 cu = g_cull[i];
        const bool keep = (cu.x + cu.z >= tX0) && (cu.x - cu.z <= tX1) &&
                          (cu.y + cu.w >= tY0) && (cu.y - cu.w <= tY1);

        const unsigned m = __ballot_sync(0xffffffffu, keep);
        if (lane == 0) sWarp[wid] = __popc(m);
        __syncthreads();

        int off = 0, total = 0;
#pragma unroll
        for (int w = 0; w < 8; ++w) {
            int cw = sWarp[w];
            if (w < wid) off += cw;
            total += cw;
        }

        if (keep) {
            const int slot = off + __popc(m & ((1u << lane) - 1u));
            sP[slot][0] = g_parm[i * 3 + 0];
            sP[slot][1] = g_parm[i * 3 + 1];
            sP[slot][2] = g_parm[i * 3 + 2];
        }
        __syncthreads();

        for (int j = 0; j < total; ++j) {
            const float4 p0 = sP[j][0];
            const float4 p1 = sP[j][1];
            const float4 p2 = sP[j][2];

            const float dx = px - p0.x;
            const float dy = py - p0.y;
            float a = fmaf(p0.z, dx, p0.w * dy);
            float b = fmaf(p1.x, dx, p1.y * dy);

#pragma unroll
            for (int k = 0; k < PPT; ++k) {
                const float t = fmaf(a, -a, -b * b);   // -(a^2 + b^2)
                float g;
                asm("ex2.approx.ftz.f32 %0, %1;" : "=f"(g) : "f"(t));
                aR[k] = fmaf(g, p2.x, aR[k]);
                aG[k] = fmaf(g, p2.y, aG[k]);
                aB[k] = fmaf(g, p2.z, aB[k]);
                if (k < PPT - 1) { a += p1.z; b += p1.w; }
            }
        }
        __syncthreads();  // protect sP / sWarp before next batch rewrites them
    }

#pragma unroll
    for (int k = 0; k < PPT; ++k) {
        const int y = y0 + 8 * k;
        const int idx = (y * RES + x) * 3;
        out[idx + 0] = aR[k];
        out[idx + 1] = aG[k];
        out[idx + 2] = aB[k];
    }
}

extern "C" void kernel_launch(void* const* d_in, const int* in_sizes, int n_in,
                              void* d_out, int out_size) {
    (void)in_sizes; (void)n_in; (void)out_size;
    const float* blobs = (const float*)d_in[0];
    float* out = (float*)d_out;

    splat_prep_kernel<<<NBLOBS / 256, 256>>>(blobs);
    dim3 grid(RES / TILE, RES / TILE);   // 16 x 16 tiles
    dim3 block(32, 8);
    splat_render_kernel<<<grid, block>>>(out);
}

// round 4
// speedup vs baseline: 1.2277x; 1.2277x over previous
#include <cuda_runtime.h>

#define RES 512
#define NBLOBS 2048
#define TILE 32          // 32x32 pixel tile
#define BXD 32           // block x
#define BYD 4            // block y
#define NT 128           // threads per CTA
#define PPT 8            // pixels per thread (stride BYD rows)
#define QCUT 5.0f        // cutoff in sigma units; exp(-12.5) ~ 3.7e-6

// Scratch (no allocations allowed): per-blob cull box + derived params.
__device__ float4 g_cull[NBLOBS];          // (bx, by, ex, ey)
__device__ float4 g_parm[NBLOBS * 3];      // (bx,by,A,B) (C,D,m1,m2) (r,g,b,c0)

// ---------------------------------------------------------------------------
// Prep: per-blob derived parameters.
//   a = (c*dx + s*dy) * kk/sx ,  b = (-s*dx + c*dy) * kk/sy , kk = sqrt(0.5*log2e)
//   g = exp(-0.5*((xr/sx)^2+(yr/sy)^2)) = 2^(-(a^2+b^2))
// Second-difference constants for y-stepping by dlt = BYD/RES:
//   da = B*dlt, db = D*dlt
//   m1 = -2*da, m2 = -2*db, c0 = -(da^2+db^2), dd = 2*c0
// ---------------------------------------------------------------------------
__global__ void splat_prep_kernel(const float* __restrict__ blobs) {
    int i = blockIdx.x * blockDim.x + threadIdx.x;
    if (i >= NBLOBS) return;
    const float* bl = blobs + i * 8;
    float bx = bl[0], by = bl[1];
    float sx = bl[2], sy = bl[3];
    float rot = bl[4];
    float cr = bl[5], cg = bl[6], cb = bl[7];

    float s, c;
    sincosf(rot, &s, &c);

    const float kk = 0.84932180f;      // sqrt(0.5 * log2(e))
    float isx = kk / sx;
    float isy = kk / sy;
    float A = c * isx, B = s * isx;    // a = A*dx + B*dy
    float C = -s * isy, D = c * isy;   // b = C*dx + D*dy

    const float dlt = (float)BYD / (float)RES;
    float da = B * dlt;
    float db = D * dlt;
    float m1 = -2.0f * da;
    float m2 = -2.0f * db;
    float c0 = -(da * da + db * db);

    // AABB half-extents of the QCUT-sigma ellipse
    float ex = QCUT * sqrtf(c * c * sx * sx + s * s * sy * sy);
    float ey = QCUT * sqrtf(s * s * sx * sx + c * c * sy * sy);

    g_cull[i] = make_float4(bx, by, ex, ey);
    g_parm[i * 3 + 0] = make_float4(bx, by, A, B);
    g_parm[i * 3 + 1] = make_float4(C, D, m1, m2);
    g_parm[i * 3 + 2] = make_float4(cr, cg, cb, c0);
}

// ---------------------------------------------------------------------------
// Render: one CTA per 32x32 tile; 128 threads (32x4); 8 pixels/thread.
// Per 128-blob batch: order-preserving ballot/prefix compaction of survivors
// into shared, then every thread evaluates the survivor list.
// ---------------------------------------------------------------------------
__global__ void __launch_bounds__(NT) splat_render_kernel(float* __restrict__ out) {
    __shared__ float4 sP[NT][3];
    __shared__ int sWarp[NT / 32];

    const int tx = threadIdx.x;            // 0..31
    const int ty = threadIdx.y;            // 0..3
    const int tid = ty * BXD + tx;
    const int lane = tid & 31;
    const int wid = tid >> 5;

    const int x = blockIdx.x * TILE + tx;
    const int y0 = blockIdx.y * TILE + ty;
    const float inv = 1.0f / (float)RES;
    const float px = ((float)x + 0.5f) * inv;
    const float py = ((float)y0 + 0.5f) * inv;

    const float tw = (float)TILE * inv;
    const float tX0 = (float)blockIdx.x * tw;
    const float tX1 = tX0 + tw;
    const float tY0 = (float)blockIdx.y * tw;
    const float tY1 = tY0 + tw;

    float aR[PPT], aG[PPT], aB[PPT];
#pragma unroll
    for (int k = 0; k < PPT; ++k) { aR[k] = 0.0f; aG[k] = 0.0f; aB[k] = 0.0f; }

    for (int base = 0; base < NBLOBS; base += NT) {
        const int i = base + tid;
        const float4 cu = g_cull[i];
        const bool keep = (cu.x + cu.z >= tX0) && (cu.x - cu.z <= tX1) &&
                          (cu.y + cu.w >= tY0) && (cu.y - cu.w <= tY1);

        const unsigned m = __ballot_sync(0xffffffffu, keep);
        if (lane == 0) sWarp[wid] = __popc(m);
        __syncthreads();

        int off = 0, total = 0;
#pragma unroll
        for (int w = 0; w < NT / 32; ++w) {
            int cw = sWarp[w];
            if (w < wid) off += cw;
            total += cw;
        }

        if (keep) {
            const int slot = off + __popc(m & ((1u << lane) - 1u));
            sP[slot][0] = g_parm[i * 3 + 0];
            sP[slot][1] = g_parm[i * 3 + 1];
            sP[slot][2] = g_parm[i * 3 + 2];
        }
        __syncthreads();

        for (int j = 0; j < total; ++j) {
            const float4 p0 = sP[j][0];
            const float4 p1 = sP[j][1];
            const float4 p2 = sP[j][2];

            const float dx = px - p0.x;
            const float dy = py - p0.y;
            float a = fmaf(p0.z, dx, p0.w * dy);
            float b = fmaf(p1.x, dx, p1.y * dy);
            float t = fmaf(a, -a, -b * b);                       // t0
            float d = fmaf(a, p1.z, fmaf(b, p1.w, p2.w));        // first difference
            const float dd = p2.w + p2.w;                        // second difference

#pragma unroll
            for (int k = 0; k < PPT; ++k) {
                float g;
                asm("ex2.approx.ftz.f32 %0, %1;" : "=f"(g) : "f"(t));
                aR[k] = fmaf(g, p2.x, aR[k]);
                aG[k] = fmaf(g, p2.y, aG[k]);
                aB[k] = fmaf(g, p2.z, aB[k]);
                if (k < PPT - 1) { t += d; d += dd; }
            }
        }
        __syncthreads();  // protect sP / sWarp before next batch rewrites them
    }

#pragma unroll
    for (int k = 0; k < PPT; ++k) {
        const int y = y0 + BYD * k;
        const int idx = (y * RES + x) * 3;
        out[idx + 0] = aR[k];
        out[idx + 1] = aG[k];
        out[idx + 2] = aB[k];
    }
}

extern "C" void kernel_launch(void* const* d_in, const int* in_sizes, int n_in,
                              void* d_out, int out_size) {
    (void)in_sizes; (void)n_in; (void)out_size;
    const float* blobs = (const float*)d_in[0];
    float* out = (float*)d_out;

    splat_prep_kernel<<<NBLOBS / 256, 256>>>(blobs);
    dim3 grid(RES / TILE, RES / TILE);   // 16 x 16 tiles
    dim3 block(BXD, BYD);
    splat_render_kernel<<<grid, block>>>(out);
}

// round 5
// speedup vs baseline: 1.3749x; 1.1198x over previous
#include <cuda_runtime.h>

#define RES 512
#define NBLOBS 2048
#define TILE_X 32
#define TILE_Y 16
#define BXD 32
#define BYD 4
#define NT 128           // threads per CTA
#define PPT 4            // pixels per thread (stride BYD rows)
#define QCUT 5.0f        // cutoff in sigma units; exp(-12.5) ~ 3.7e-6

// Scratch (no allocations allowed): per-blob cull box + derived params.
__device__ float4 g_cull[NBLOBS];          // (bx, by, ex, ey)
__device__ float4 g_parm[NBLOBS * 3];      // (bx,by,A,B) (C,D,m1,m2) (r,g,b,c0)

// ---------------------------------------------------------------------------
// Prep: per-blob derived parameters.
//   a = (c*dx + s*dy) * kk/sx ,  b = (-s*dx + c*dy) * kk/sy , kk = sqrt(0.5*log2e)
//   g = exp(-0.5*((xr/sx)^2+(yr/sy)^2)) = 2^(-(a^2+b^2))
// Second-difference constants for y-stepping by dlt = BYD/RES:
//   t(k) = -(a+k*da)^2-(b+k*db)^2 :  d0 = m1*a+m2*b+c0, dd = 2*c0
// ---------------------------------------------------------------------------
__global__ void splat_prep_kernel(const float* __restrict__ blobs) {
    int i = blockIdx.x * blockDim.x + threadIdx.x;
    if (i >= NBLOBS) return;
    const float* bl = blobs + i * 8;
    float bx = bl[0], by = bl[1];
    float sx = bl[2], sy = bl[3];
    float rot = bl[4];
    float cr = bl[5], cg = bl[6], cb = bl[7];

    float s, c;
    sincosf(rot, &s, &c);

    const float kk = 0.84932180f;      // sqrt(0.5 * log2(e))
    float isx = kk / sx;
    float isy = kk / sy;
    float A = c * isx, B = s * isx;    // a = A*dx + B*dy
    float C = -s * isy, D = c * isy;   // b = C*dx + D*dy

    const float dlt = (float)BYD / (float)RES;
    float da = B * dlt;
    float db = D * dlt;
    float m1 = -2.0f * da;
    float m2 = -2.0f * db;
    float c0 = -(da * da + db * db);

    // AABB half-extents of the QCUT-sigma ellipse
    float ex = QCUT * sqrtf(c * c * sx * sx + s * s * sy * sy);
    float ey = QCUT * sqrtf(s * s * sx * sx + c * c * sy * sy);

    g_cull[i] = make_float4(bx, by, ex, ey);
    g_parm[i * 3 + 0] = make_float4(bx, by, A, B);
    g_parm[i * 3 + 1] = make_float4(C, D, m1, m2);
    g_parm[i * 3 + 2] = make_float4(cr, cg, cb, c0);
}

// ---------------------------------------------------------------------------
// Render: one CTA per 32x16 tile; 128 threads (32x4); 4 pixels/thread.
// Per 128-blob batch: order-preserving ballot/prefix compaction of survivors
// into shared, then every thread evaluates the survivor list (2-way unrolled
// to build two independent pair pipelines per warp).
// ---------------------------------------------------------------------------
__global__ void __launch_bounds__(NT) splat_render_kernel(float* __restrict__ out) {
    __shared__ float4 sP[NT][3];
    __shared__ int sWarp[NT / 32];

    const int tx = threadIdx.x;            // 0..31
    const int ty = threadIdx.y;            // 0..3
    const int tid = ty * BXD + tx;
    const int lane = tid & 31;
    const int wid = tid >> 5;

    const int x = blockIdx.x * TILE_X + tx;
    const int y0 = blockIdx.y * TILE_Y + ty;
    const float inv = 1.0f / (float)RES;
    const float px = ((float)x + 0.5f) * inv;
    const float py = ((float)y0 + 0.5f) * inv;

    const float tX0 = (float)blockIdx.x * ((float)TILE_X * inv);
    const float tX1 = tX0 + (float)TILE_X * inv;
    const float tY0 = (float)blockIdx.y * ((float)TILE_Y * inv);
    const float tY1 = tY0 + (float)TILE_Y * inv;

    float aR[PPT], aG[PPT], aB[PPT];
#pragma unroll
    for (int k = 0; k < PPT; ++k) { aR[k] = 0.0f; aG[k] = 0.0f; aB[k] = 0.0f; }

    for (int base = 0; base < NBLOBS; base += NT) {
        const int i = base + tid;
        const float4 cu = g_cull[i];
        const bool keep = (cu.x + cu.z >= tX0) && (cu.x - cu.z <= tX1) &&
                          (cu.y + cu.w >= tY0) && (cu.y - cu.w <= tY1);

        const unsigned m = __ballot_sync(0xffffffffu, keep);
        if (lane == 0) sWarp[wid] = __popc(m);
        __syncthreads();

        int off = 0, total = 0;
#pragma unroll
        for (int w = 0; w < NT / 32; ++w) {
            int cw = sWarp[w];
            if (w < wid) off += cw;
            total += cw;
        }

        if (keep) {
            const int slot = off + __popc(m & ((1u << lane) - 1u));
            sP[slot][0] = g_parm[i * 3 + 0];
            sP[slot][1] = g_parm[i * 3 + 1];
            sP[slot][2] = g_parm[i * 3 + 2];
        }
        __syncthreads();

#define PAIR_BODY(J)                                                          \
        {                                                                     \
            const float4 p0 = sP[(J)][0];                                     \
            const float4 p1 = sP[(J)][1];                                     \
            const float4 p2 = sP[(J)][2];                                     \
            const float dx = px - p0.x;                                       \
            const float dy = py - p0.y;                                       \
            float a = fmaf(p0.z, dx, p0.w * dy);                              \
            float b = fmaf(p1.x, dx, p1.y * dy);                              \
            float t = fmaf(a, -a, -b * b);                                    \
            float d = fmaf(a, p1.z, fmaf(b, p1.w, p2.w));                     \
            const float dd = p2.w + p2.w;                                     \
            _Pragma("unroll")                                                 \
            for (int k = 0; k < PPT; ++k) {                                   \
                float g;                                                      \
                asm("ex2.approx.ftz.f32 %0, %1;" : "=f"(g) : "f"(t));         \
                aR[k] = fmaf(g, p2.x, aR[k]);                                 \
                aG[k] = fmaf(g, p2.y, aG[k]);                                 \
                aB[k] = fmaf(g, p2.z, aB[k]);                                 \
                if (k < PPT - 1) { t += d; d += dd; }                         \
            }                                                                 \
        }

        int j = 0;
        for (; j + 2 <= total; j += 2) {
            PAIR_BODY(j)
            PAIR_BODY(j + 1)
        }
        if (j < total) {
            PAIR_BODY(j)
        }
#undef PAIR_BODY

        __syncthreads();  // protect sP / sWarp before next batch rewrites them
    }

#pragma unroll
    for (int k = 0; k < PPT; ++k) {
        const int y = y0 + BYD * k;
        const int idx = (y * RES + x) * 3;
        out[idx + 0] = aR[k];
        out[idx + 1] = aG[k];
        out[idx + 2] = aB[k];
    }
}

extern "C" void kernel_launch(void* const* d_in, const int* in_sizes, int n_in,
                              void* d_out, int out_size) {
    (void)in_sizes; (void)n_in; (void)out_size;
    const float* blobs = (const float*)d_in[0];
    float* out = (float*)d_out;

    splat_prep_kernel<<<NBLOBS / 256, 256>>>(blobs);
    dim3 grid(RES / TILE_X, RES / TILE_Y);   // 16 x 32 tiles
    dim3 block(BXD, BYD);
    splat_render_kernel<<<grid, block>>>(out);
}